// round 4
// baseline (speedup 1.0000x reference)
#include <cuda_runtime.h>
#include <cstdint>

#define BN   2048      // batch rows
#define NL   64        // latent dim
#define NU   16        // nuisance dim
#define NO   2048      // output dim
#define ZS   (NL + NU) // z row stride (80)
#define TM   16        // rows per decoder tile (same nuisance id)
#define NT   512       // decoder threads: thread t owns cols [4t, 4t+4)
#define MAXTILES (BN / TM)   // 128

// Device-global scratch (no allocations allowed).
// g_hist starts zeroed (static init); each decoder launch re-zeroes it for the
// next identical replay (last-block-resets). Deterministic: every call does
// the same work on the same inputs.
__device__ int g_hist[NU];
__device__ int g_bucket[NU * BN];
__device__ int g_done = 0;

// ---------- packed f32x2 helpers (Blackwell, PTX-only path) ----------
typedef unsigned long long ull;
__device__ __forceinline__ void fma2(ull& d, ull a, ull b) {
    asm("fma.rn.f32x2 %0, %1, %2, %0;" : "+l"(d) : "l"(a), "l"(b));
}
__device__ __forceinline__ ull add2(ull a, ull b) {
    ull d; asm("add.rn.f32x2 %0, %1, %2;" : "=l"(d) : "l"(a), "l"(b)); return d;
}
__device__ __forceinline__ ull pack2(float x, float y) {
    ull r; asm("mov.b64 %0, {%1, %2};" : "=l"(r) : "f"(x), "f"(y)); return r;
}
__device__ __forceinline__ void unpack2(ull v, float& x, float& y) {
    asm("mov.b64 {%0, %1}, %2;" : "=f"(x), "=f"(y) : "l"(v));
}
__device__ __forceinline__ float warpMax(float v) {
    #pragma unroll
    for (int o = 16; o > 0; o >>= 1) v = fmaxf(v, __shfl_xor_sync(0xFFFFFFFFu, v, o));
    return v;
}
__device__ __forceinline__ float warpSum(float v) {
    #pragma unroll
    for (int o = 16; o > 0; o >>= 1) v += __shfl_xor_sync(0xFFFFFFFFu, v, o);
    return v;
}

// ---------- kernel 1: argmax id + bucket scatter + theta ----------
// One thread per row (and per theta element). g_hist pre-zeroed (see above).
__global__ void assign_kernel(const float* __restrict__ z,
                              const float* __restrict__ px_r,
                              float* __restrict__ out) {
    int r = blockIdx.x * blockDim.x + threadIdx.x;   // 0..2047
    out[(size_t)BN * NO + r] = expf(px_r[r]);        // theta

    const float4* zn = (const float4*)(z + (size_t)r * ZS + NL);  // 16B aligned
    float4 a = zn[0], b = zn[1], c = zn[2], d = zn[3];
    float v[NU] = {a.x, a.y, a.z, a.w, b.x, b.y, b.z, b.w,
                   c.x, c.y, c.z, c.w, d.x, d.y, d.z, d.w};
    int best = 0; float bv = v[0];
    #pragma unroll
    for (int j = 1; j < NU; j++)
        if (v[j] > bv) { bv = v[j]; best = j; }      // first-max wins (jnp.argmax)
    int pos = atomicAdd(&g_hist[best], 1);
    g_bucket[best * BN + pos] = r;
}

// ---------- kernel 2: grouped fused decoder (w+s fused via ADD2) ----------
// grid = (NU, MAXTILES). Block (id, tile): TM rows of group id; thread t owns
// cols [4t, 4t+4) as two f32x2 accumulators per row, initialized to offsets.
__global__ __launch_bounds__(NT, 1)
void decoder_kernel(const float* __restrict__ z,
                    const float* __restrict__ size_factor,
                    const float* __restrict__ amat_w,
                    const float* __restrict__ amat_site,
                    const float* __restrict__ offsets,
                    float* __restrict__ out) {
    const int id   = blockIdx.x;
    const int tile = blockIdx.y;
    const int cnt  = g_hist[id];
    const int base = tile * TM;
    const int tid  = threadIdx.x;
    const int wid  = tid >> 5;
    const int col  = tid * 4;

    __shared__ __align__(16) float2 zdup[NL][TM];  // (v,v) per (l,row)
    __shared__ float sf_s[TM];
    __shared__ int   rows_s[TM];
    __shared__ float wred[TM * 16];
    __shared__ float rowmax_s[TM];
    __shared__ float rowsum_s[TM];

    if (base < cnt) {
        const int nrows = min(TM, cnt - base);

        if (tid < TM) {
            int row = (tid < nrows) ? g_bucket[id * BN + base + tid] : -1;
            rows_s[tid] = row;
            sf_s[tid] = (row >= 0) ? size_factor[row] : 1.0f;
        }
        __syncthreads();

        // Stage z duplicated: zdup[l][r] = (z[row r][l], same)
        for (int i = tid; i < TM * NL; i += NT) {
            int r = i & (TM - 1), l = i >> 4;
            int row = rows_s[r];
            float v = (row >= 0) ? z[(size_t)row * ZS + l] : 0.0f;
            zdup[l][r] = make_float2(v, v);
        }
        __syncthreads();

        const float* W = amat_w + col;
        const float* S = amat_site + (size_t)id * NL * NO + col;
        const float4 off4 = *(const float4*)(offsets + (size_t)id * NO + col);

        ull acc[TM][2];
        const ull off01 = pack2(off4.x, off4.y);
        const ull off23 = pack2(off4.z, off4.w);
        #pragma unroll
        for (int r = 0; r < TM; r++) { acc[r][0] = off01; acc[r][1] = off23; }

        #pragma unroll 4
        for (int l = 0; l < NL; l++) {
            ulonglong2 wp = *(const ulonglong2*)(W + (size_t)l * NO);
            ulonglong2 sp = *(const ulonglong2*)(S + (size_t)l * NO);
            ull ap0 = add2(wp.x, sp.x);                // combined cols (c0,c1)
            ull ap1 = add2(wp.y, sp.y);                // combined cols (c2,c3)
            const ulonglong2* zl = (const ulonglong2*)zdup[l];
            #pragma unroll
            for (int rp = 0; rp < TM / 2; rp++) {
                ulonglong2 zp = zl[rp];                // LDS.128 broadcast, 2 rows
                fma2(acc[2 * rp][0],     ap0, zp.x);
                fma2(acc[2 * rp][1],     ap1, zp.x);
                fma2(acc[2 * rp + 1][0], ap0, zp.y);
                fma2(acc[2 * rp + 1][1], ap1, zp.y);
            }
        }

        // Unpack logits
        float lv[TM][4];
        #pragma unroll
        for (int r = 0; r < TM; r++) {
            unpack2(acc[r][0], lv[r][0], lv[r][1]);
            unpack2(acc[r][1], lv[r][2], lv[r][3]);
        }

        // Row max (block-wide over 2048 cols)
        #pragma unroll
        for (int r = 0; r < TM; r++) {
            float m = fmaxf(fmaxf(lv[r][0], lv[r][1]), fmaxf(lv[r][2], lv[r][3]));
            m = warpMax(m);
            if ((tid & 31) == 0) wred[r * 16 + wid] = m;
        }
        __syncthreads();
        if (tid < TM) {
            float m = wred[tid * 16];
            #pragma unroll
            for (int w = 1; w < 16; w++) m = fmaxf(m, wred[tid * 16 + w]);
            rowmax_s[tid] = m;
        }
        __syncthreads();

        // Exp + row sum
        #pragma unroll
        for (int r = 0; r < TM; r++) {
            const float rm = rowmax_s[r];
            float e0 = __expf(lv[r][0] - rm);
            float e1 = __expf(lv[r][1] - rm);
            float e2 = __expf(lv[r][2] - rm);
            float e3 = __expf(lv[r][3] - rm);
            lv[r][0] = e0; lv[r][1] = e1; lv[r][2] = e2; lv[r][3] = e3;
            float s = warpSum(e0 + e1 + e2 + e3);
            if ((tid & 31) == 0) wred[r * 16 + wid] = s;
        }
        __syncthreads();
        if (tid < TM) {
            float s = wred[tid * 16];
            #pragma unroll
            for (int w = 1; w < 16; w++) s += wred[tid * 16 + w];
            rowsum_s[tid] = s;
        }
        __syncthreads();

        // Scale and write mu (coalesced float4)
        #pragma unroll
        for (int r = 0; r < TM; r++) {
            int row = rows_s[r];
            if (row >= 0) {
                float sc = sf_s[r] / rowsum_s[r];
                float4 o;
                o.x = lv[r][0] * sc; o.y = lv[r][1] * sc;
                o.z = lv[r][2] * sc; o.w = lv[r][3] * sc;
                *(float4*)(out + (size_t)row * NO + col) = o;
            }
        }
    }

    // Last-block-resets: re-zero g_hist for the next identical replay.
    // Every block (including early-exit ones) arrives here after its g_hist read.
    if (tid == 0) {
        int d = atomicAdd(&g_done, 1);
        if (d == (int)(gridDim.x * gridDim.y) - 1) {
            g_done = 0;
            #pragma unroll
            for (int i = 0; i < NU; i++) g_hist[i] = 0;
        }
    }
}

extern "C" void kernel_launch(void* const* d_in, const int* in_sizes, int n_in,
                              void* d_out, int out_size) {
    const float* z    = (const float*)d_in[0];
    const float* sf   = (const float*)d_in[1];
    const float* aw   = (const float*)d_in[2];
    const float* as   = (const float*)d_in[3];
    const float* off  = (const float*)d_in[4];
    const float* pxr  = (const float*)d_in[5];
    float* out = (float*)d_out;

    assign_kernel<<<BN / 256, 256>>>(z, pxr, out);
    dim3 grid(NU, MAXTILES);
    decoder_kernel<<<grid, NT>>>(z, sf, aw, as, off, out);
}